// round 1
// baseline (speedup 1.0000x reference)
#include <cuda_runtime.h>
#include <math.h>

#define N_NODES 8192
#define N_BONDS 16384
#define EMBED 32
#define HIDDEN 256
#define DEPTH 10
#define NUM_GRAPHS 256
#define G3 96  // 3*EMBED

// ---------------- scratch (static device globals; no allocation) ----------------
__device__ float g_h[N_NODES * EMBED];            // node state (fp32), updated in place per depth
__device__ float g_nei[2][N_NODES * EMBED];       // partial neighbor sums (j split in 2)
__device__ float g_msg[N_NODES * HIDDEN];         // message vectors
__device__ float g_invdeg[N_NODES];
__device__ float g_hasnei[N_NODES];
__device__ float g_pool_sum[NUM_GRAPHS * EMBED];
__device__ float g_pool_cnt[NUM_GRAPHS];

// ---------------- init: h = atom_emb[af], bond emb -> out, zero pool accumulators ----
__global__ void k_init(const int* __restrict__ af, const int* __restrict__ bf,
                       const float* __restrict__ atab, const float* __restrict__ btab,
                       float* __restrict__ out) {
    int idx = blockIdx.x * 256 + threadIdx.x;
    if (idx < N_BONDS * EMBED) {
        out[N_NODES * EMBED + idx] = btab[bf[idx >> 5] * EMBED + (idx & 31)];
    }
    if (idx < N_NODES * EMBED) {
        g_h[idx] = atab[af[idx >> 5] * EMBED + (idx & 31)];
    }
    if (idx < NUM_GRAPHS * EMBED) g_pool_sum[idx] = 0.f;
    if (idx < NUM_GRAPHS) g_pool_cnt[idx] = 0.f;
}

// ---------------- degree per row ----------------
__global__ void k_degree(const int* __restrict__ adj) {
    int row = blockIdx.x;
    const int4* a = (const int4*)(adj + (size_t)row * N_NODES);
    int s = 0;
    for (int i = threadIdx.x; i < N_NODES / 4; i += 256) {
        int4 v = a[i];
        s += (v.x != 0) + (v.y != 0) + (v.z != 0) + (v.w != 0);
    }
#pragma unroll
    for (int off = 16; off; off >>= 1) s += __shfl_down_sync(0xffffffffu, s, off);
    __shared__ int red[8];
    if ((threadIdx.x & 31) == 0) red[threadIdx.x >> 5] = s;
    __syncthreads();
    if (threadIdx.x == 0) {
        int tot = 0;
#pragma unroll
        for (int i = 0; i < 8; i++) tot += red[i];
        float deg = (float)tot;
        g_invdeg[row] = 1.0f / fmaxf(deg, 1.0f);
        g_hasnei[row] = tot > 0 ? 1.0f : 0.0f;
    }
}

// ---------------- nei_sum = A @ h  (fp32, SMEM tiled; grid.y splits j range) -------
// Block: 256 threads, 32 rows; thread owns (row r, 4 cols). h chunk 128 nodes staged.
__global__ void __launch_bounds__(256) k_neisum(const int* __restrict__ adj) {
    __shared__ float sh_h[128 * 36];   // [jj][c], pitch 36 (16B-aligned, conflict-free reads)
    __shared__ float sh_a[32 * 132];   // [r][jj], pitch 132
    int row0 = blockIdx.x * 32;
    int half = blockIdx.y;
    int t = threadIdx.x;
    int r = t >> 3;
    int c4 = (t & 7) << 2;
    float4 acc = make_float4(0.f, 0.f, 0.f, 0.f);
    int jbase = half * (N_NODES / 2);
    for (int chunk = 0; chunk < (N_NODES / 2) / 128; ++chunk) {
        int j0 = jbase + chunk * 128;
#pragma unroll
        for (int k = 0; k < 4; k++) {  // 1024 float4 of h chunk
            int idx = t + k * 256;
            int jj = idx >> 3, cc = (idx & 7) << 2;
            float4 v = *(const float4*)&g_h[(size_t)(j0 + jj) * EMBED + cc];
            *(float4*)&sh_h[jj * 36 + cc] = v;
        }
#pragma unroll
        for (int k = 0; k < 4; k++) {  // 1024 int4 of adjacency, convert to {0,1} float
            int idx = t + k * 256;
            int rr = idx >> 5;
            int q = (idx & 31) << 2;
            int4 v = *(const int4*)&adj[(size_t)(row0 + rr) * N_NODES + j0 + q];
            float4 f = make_float4(v.x != 0 ? 1.f : 0.f, v.y != 0 ? 1.f : 0.f,
                                   v.z != 0 ? 1.f : 0.f, v.w != 0 ? 1.f : 0.f);
            *(float4*)&sh_a[rr * 132 + q] = f;
        }
        __syncthreads();
        const float* ap = &sh_a[r * 132];
        const float* hp = &sh_h[c4];
#pragma unroll 4
        for (int jj = 0; jj < 128; jj++) {
            float a = ap[jj];
            float4 hv = *(const float4*)&hp[jj * 36];
            acc.x = fmaf(a, hv.x, acc.x);
            acc.y = fmaf(a, hv.y, acc.y);
            acc.z = fmaf(a, hv.z, acc.z);
            acc.w = fmaf(a, hv.w, acc.w);
        }
        __syncthreads();
    }
    *(float4*)&g_nei[half][(size_t)(row0 + r) * EMBED + c4] = acc;
}

// ---------------- msg = [h | nei_mean] @ msg_W^T + b, zeroed where no neighbors ----
// 32 rows/block; W staged transposed in dynamic SMEM; thread tile 4 rows x 8 outs.
#define MSG_SMEM_FLOATS (32 * 68 + 64 * 260)
__global__ void __launch_bounds__(256) k_msg(const float* __restrict__ Wd,
                                             const float* __restrict__ bd) {
    extern __shared__ float sm[];
    float* x_s = sm;             // [32][68]  (h || nei_mean)
    float* W_s = sm + 32 * 68;   // [k=64][o pitch 260]
    int row0 = blockIdx.x * 32;
    int t = threadIdx.x;
    for (int idx = t; idx < 32 * EMBED; idx += 256) {
        int r = idx >> 5, e = idx & 31;
        int node = row0 + r;
        x_s[r * 68 + e] = g_h[node * EMBED + e];
        x_s[r * 68 + 32 + e] =
            (g_nei[0][node * EMBED + e] + g_nei[1][node * EMBED + e]) * g_invdeg[node];
    }
    for (int idx = t; idx < HIDDEN * 64; idx += 256) {
        int o = idx >> 6, k = idx & 63;   // coalesced read, transposed store
        W_s[k * 260 + o] = Wd[idx];
    }
    __syncthreads();
    int rb = (t >> 5) * 4;
    int ob = (t & 31) * 8;
    float acc[4][8];
#pragma unroll
    for (int i = 0; i < 4; i++)
#pragma unroll
        for (int j = 0; j < 8; j++) acc[i][j] = 0.f;
    for (int k = 0; k < 64; k++) {
        float xv[4];
#pragma unroll
        for (int i = 0; i < 4; i++) xv[i] = x_s[(rb + i) * 68 + k];
        float4 w0 = *(const float4*)&W_s[k * 260 + ob];
        float4 w1 = *(const float4*)&W_s[k * 260 + ob + 4];
        float w[8] = {w0.x, w0.y, w0.z, w0.w, w1.x, w1.y, w1.z, w1.w};
#pragma unroll
        for (int i = 0; i < 4; i++)
#pragma unroll
            for (int j = 0; j < 8; j++) acc[i][j] = fmaf(xv[i], w[j], acc[i][j]);
    }
#pragma unroll
    for (int i = 0; i < 4; i++) {
        int node = row0 + rb + i;
        float hn = g_hasnei[node];
        float4 o0, o1;
        o0.x = (acc[i][0] + bd[ob + 0]) * hn;
        o0.y = (acc[i][1] + bd[ob + 1]) * hn;
        o0.z = (acc[i][2] + bd[ob + 2]) * hn;
        o0.w = (acc[i][3] + bd[ob + 3]) * hn;
        o1.x = (acc[i][4] + bd[ob + 4]) * hn;
        o1.y = (acc[i][5] + bd[ob + 5]) * hn;
        o1.z = (acc[i][6] + bd[ob + 6]) * hn;
        o1.w = (acc[i][7] + bd[ob + 7]) * hn;
        *(float4*)&g_msg[(size_t)node * HIDDEN + ob] = o0;
        *(float4*)&g_msg[(size_t)node * HIDDEN + ob + 4] = o1;
    }
}

// ---------------- GRU step (fused gi/gh GEMMs + gates), h updated in place ----------
#define GRU_SMEM_FLOATS (32 * 256 + 32 * 32 + 256 * 100 + 32 * 100 + 32 * 100 + 32 * 100)
__global__ void __launch_bounds__(256) k_gru(const float* __restrict__ Wih,
                                             const float* __restrict__ Whh,
                                             const float* __restrict__ bih,
                                             const float* __restrict__ bhh) {
    extern __shared__ float sm[];
    float* msg_s = sm;                    // [32][256]
    float* h_s   = msg_s + 32 * 256;      // [32][32]
    float* Wih_s = h_s + 32 * 32;         // [k=256][g pitch 100]
    float* Whh_s = Wih_s + 256 * 100;     // [k=32][g pitch 100]
    float* gi_s  = Whh_s + 32 * 100;      // [32][g pitch 100]
    float* gh_s  = gi_s + 32 * 100;       // [32][g pitch 100]
    int row0 = blockIdx.x * 32;
    int t = threadIdx.x;
    for (int idx = t; idx < 32 * HIDDEN; idx += 256) {
        int r = idx >> 8;
        msg_s[idx] = g_msg[(size_t)(row0 + r) * HIDDEN + (idx & 255)];
    }
    for (int idx = t; idx < 32 * EMBED; idx += 256) {
        int r = idx >> 5;
        h_s[idx] = g_h[(size_t)(row0 + r) * EMBED + (idx & 31)];
    }
    for (int idx = t; idx < G3 * HIDDEN; idx += 256) {
        int g = idx >> 8, k = idx & 255;
        Wih_s[k * 100 + g] = Wih[idx];
    }
    for (int idx = t; idx < G3 * EMBED; idx += 256) {
        int g = idx >> 5, k = idx & 31;
        Whh_s[k * 100 + g] = Whh[idx];
    }
    __syncthreads();
    int rb = (t >> 5) * 4;
    int gb = (t & 31) * 3;
    float gi[12], gh[12];
#pragma unroll
    for (int i = 0; i < 12; i++) { gi[i] = 0.f; gh[i] = 0.f; }
    for (int k = 0; k < HIDDEN; k++) {
        float w0 = Wih_s[k * 100 + gb];
        float w1 = Wih_s[k * 100 + gb + 1];
        float w2 = Wih_s[k * 100 + gb + 2];
#pragma unroll
        for (int i = 0; i < 4; i++) {
            float m = msg_s[(rb + i) * 256 + k];
            gi[i * 3 + 0] = fmaf(m, w0, gi[i * 3 + 0]);
            gi[i * 3 + 1] = fmaf(m, w1, gi[i * 3 + 1]);
            gi[i * 3 + 2] = fmaf(m, w2, gi[i * 3 + 2]);
        }
    }
    for (int k = 0; k < EMBED; k++) {
        float w0 = Whh_s[k * 100 + gb];
        float w1 = Whh_s[k * 100 + gb + 1];
        float w2 = Whh_s[k * 100 + gb + 2];
#pragma unroll
        for (int i = 0; i < 4; i++) {
            float hv = h_s[(rb + i) * 32 + k];
            gh[i * 3 + 0] = fmaf(hv, w0, gh[i * 3 + 0]);
            gh[i * 3 + 1] = fmaf(hv, w1, gh[i * 3 + 1]);
            gh[i * 3 + 2] = fmaf(hv, w2, gh[i * 3 + 2]);
        }
    }
    float bi0 = bih[gb], bi1 = bih[gb + 1], bi2 = bih[gb + 2];
    float bh0 = bhh[gb], bh1 = bhh[gb + 1], bh2 = bhh[gb + 2];
#pragma unroll
    for (int i = 0; i < 4; i++) {
        gi_s[(rb + i) * 100 + gb + 0] = gi[i * 3 + 0] + bi0;
        gi_s[(rb + i) * 100 + gb + 1] = gi[i * 3 + 1] + bi1;
        gi_s[(rb + i) * 100 + gb + 2] = gi[i * 3 + 2] + bi2;
        gh_s[(rb + i) * 100 + gb + 0] = gh[i * 3 + 0] + bh0;
        gh_s[(rb + i) * 100 + gb + 1] = gh[i * 3 + 1] + bh1;
        gh_s[(rb + i) * 100 + gb + 2] = gh[i * 3 + 2] + bh2;
    }
    __syncthreads();
    for (int idx = t; idx < 32 * EMBED; idx += 256) {
        int r = idx >> 5, e = idx & 31;
        float ir = gi_s[r * 100 + e],      hr = gh_s[r * 100 + e];
        float iz = gi_s[r * 100 + 32 + e], hz = gh_s[r * 100 + 32 + e];
        float in_ = gi_s[r * 100 + 64 + e], hn = gh_s[r * 100 + 64 + e];
        float rg = 1.f / (1.f + expf(-(ir + hr)));
        float z  = 1.f / (1.f + expf(-(iz + hz)));
        float n  = tanhf(in_ + rg * hn);
        float hp = h_s[r * 32 + e];
        g_h[(size_t)(row0 + r) * EMBED + e] = (1.f - z) * n + z * hp;
    }
}

// ---------------- pooling: copy h to out + segment sums via atomics ----------------
__global__ void k_pool(const int* __restrict__ bidx, float* __restrict__ out) {
    int idx = blockIdx.x * 256 + threadIdx.x;
    if (idx < N_NODES * EMBED) {
        int n = idx >> 5, e = idx & 31;
        float v = g_h[idx];
        out[idx] = v;
        int b = bidx[n];
        atomicAdd(&g_pool_sum[b * EMBED + e], v);
        if (e == 0) atomicAdd(&g_pool_cnt[b], 1.0f);
    }
}

// ---------------- graph embeddings: mean @ pool_W^T + pool_b ----------------
__global__ void __launch_bounds__(256) k_graph(const float* __restrict__ pW,
                                               const float* __restrict__ pb,
                                               float* __restrict__ out) {
    __shared__ float mean[EMBED];
    __shared__ float Ws[EMBED * HIDDEN];  // transposed: [e][o]
    int b = blockIdx.x;
    int t = threadIdx.x;
    for (int idx = t; idx < HIDDEN * EMBED; idx += 256) {
        int o = idx >> 5, e = idx & 31;
        Ws[e * HIDDEN + o] = pW[idx];
    }
    if (t < EMBED) {
        float cnt = g_pool_cnt[b];
        mean[t] = cnt > 0.f ? g_pool_sum[b * EMBED + t] / cnt : 0.f;
    }
    __syncthreads();
    float acc = pb[t];
#pragma unroll
    for (int e = 0; e < EMBED; e++) acc = fmaf(mean[e], Ws[e * HIDDEN + t], acc);
    out[(size_t)(N_NODES * EMBED + N_BONDS * EMBED) + b * HIDDEN + t] = acc;
}

// ---------------- launch ----------------
extern "C" void kernel_launch(void* const* d_in, const int* in_sizes, int n_in,
                              void* d_out, int out_size) {
    const int* af    = (const int*)d_in[0];
    const int* bf    = (const int*)d_in[1];
    const int* adj   = (const int*)d_in[2];
    const int* bidx  = (const int*)d_in[3];
    const float* atab = (const float*)d_in[4];
    const float* btab = (const float*)d_in[5];
    const float* msgW = (const float*)d_in[6];
    const float* msgb = (const float*)d_in[7];
    const float* Wih  = (const float*)d_in[8];
    const float* Whh  = (const float*)d_in[9];
    const float* bih  = (const float*)d_in[10];
    const float* bhh  = (const float*)d_in[11];
    const float* pW   = (const float*)d_in[12];
    const float* pb   = (const float*)d_in[13];
    float* out = (float*)d_out;

    cudaFuncSetAttribute(k_msg, cudaFuncAttributeMaxDynamicSharedMemorySize,
                         MSG_SMEM_FLOATS * 4);
    cudaFuncSetAttribute(k_gru, cudaFuncAttributeMaxDynamicSharedMemorySize,
                         GRU_SMEM_FLOATS * 4);

    k_init<<<(N_BONDS * EMBED + 255) / 256, 256>>>(af, bf, atab, btab, out);
    k_degree<<<N_NODES, 256>>>(adj);
    for (int d = 0; d < DEPTH; ++d) {
        k_neisum<<<dim3(N_NODES / 32, 2), 256>>>(adj);
        k_msg<<<N_NODES / 32, 256, MSG_SMEM_FLOATS * 4>>>(msgW + d * HIDDEN * 64,
                                                          msgb + d * HIDDEN);
        k_gru<<<N_NODES / 32, 256, GRU_SMEM_FLOATS * 4>>>(
            Wih + d * G3 * HIDDEN, Whh + d * G3 * EMBED, bih + d * G3, bhh + d * G3);
    }
    k_pool<<<(N_NODES * EMBED + 255) / 256, 256>>>(bidx, out);
    k_graph<<<NUM_GRAPHS, HIDDEN>>>(pW, pb, out);
}

// round 3
// speedup vs baseline: 3.8218x; 3.8218x over previous
#include <cuda_runtime.h>
#include <cuda_bf16.h>
#include <math.h>
#include <stdint.h>

#define N_NODES 8192
#define N_BONDS 16384
#define EMBED 32
#define HIDDEN 256
#define DEPTH 10
#define NUM_GRAPHS 256

// ---------------- static device scratch ----------------
// A image: fragment-ordered int8 {0,1}. Block (mb 0..511, kc 0..63) = 2048B:
//   within block: [lane 32][kt 8][8 bytes], bytes for lane t, kt:
//   rows r=t/4 (+8), k = kt*16 + (t%4)*2 (+1, +8, +9) in a-frag order.
__device__ __align__(16) uint8_t g_A8[(size_t)512 * 64 * 2048];  // 64MB
__device__ __align__(16) __nv_bfloat16 g_hT[N_NODES * 64];       // [j][hi32|lo32]
__device__ __align__(16) float g_h[N_NODES * EMBED];
__device__ __align__(16) float g_neip[4][N_NODES * EMBED];       // [khalf*2+nw]
__device__ __align__(16) float g_msg[N_NODES * HIDDEN];
__device__ float g_deg[N_NODES];
__device__ float g_pool_sum[NUM_GRAPHS * EMBED];
__device__ float g_pool_cnt[NUM_GRAPHS];

// ---------------- PTX helpers ----------------
__device__ __forceinline__ uint32_t smem_u32(const void* p) {
    uint32_t a;
    asm("{ .reg .u64 t; cvta.to.shared.u64 t, %1; cvt.u32.u64 %0, t; }" : "=r"(a) : "l"(p));
    return a;
}
__device__ __forceinline__ uint32_t prmt0(uint32_t a, uint32_t sel) {
    uint32_t d;
    asm("prmt.b32 %0, %1, 0, %2;" : "=r"(d) : "r"(a), "r"(sel));
    return d;
}
__device__ __forceinline__ void cp16(uint32_t dst, const void* src) {
    asm volatile("cp.async.cg.shared.global [%0], [%1], 16;" :: "r"(dst), "l"(src));
}
__device__ __forceinline__ void ldm_x2_trans(uint32_t* r, uint32_t addr) {
    asm volatile("ldmatrix.sync.aligned.m8n8.x2.trans.shared.b16 {%0,%1}, [%2];"
                 : "=r"(r[0]), "=r"(r[1]) : "r"(addr));
}
__device__ __forceinline__ void mma_bf16(float* c, uint32_t a0, uint32_t a1,
                                         uint32_t a2, uint32_t a3,
                                         uint32_t b0, uint32_t b1) {
    asm volatile(
        "mma.sync.aligned.m16n8k16.row.col.f32.bf16.bf16.f32 "
        "{%0,%1,%2,%3}, {%4,%5,%6,%7}, {%8,%9}, {%0,%1,%2,%3};"
        : "+f"(c[0]), "+f"(c[1]), "+f"(c[2]), "+f"(c[3])
        : "r"(a0), "r"(a1), "r"(a2), "r"(a3), "r"(b0), "r"(b1));
}

// ---------------- init ----------------
__global__ void k_init(const int* __restrict__ af, const int* __restrict__ bf,
                       const float* __restrict__ atab, const float* __restrict__ btab,
                       float* __restrict__ out) {
    int idx = blockIdx.x * 256 + threadIdx.x;
    if (idx < N_BONDS * EMBED)
        out[N_NODES * EMBED + idx] = btab[bf[idx >> 5] * EMBED + (idx & 31)];
    if (idx < N_NODES * EMBED)
        g_h[idx] = atab[af[idx >> 5] * EMBED + (idx & 31)];
    if (idx < N_NODES) g_deg[idx] = 0.f;
    if (idx < NUM_GRAPHS * EMBED) g_pool_sum[idx] = 0.f;
    if (idx < NUM_GRAPHS) g_pool_cnt[idx] = 0.f;
}

// ---------------- adjacency -> fragment-ordered int8 image + degree ----------------
// grid (512, 8), 256 threads. warp w handles block (mb=blockIdx.x, kc=blockIdx.y*8+w).
__global__ void __launch_bounds__(256) k_convA(const int* __restrict__ adj) {
    int t = threadIdx.x, lane = t & 31, w = t >> 5;
    int mb = blockIdx.x;
    int kc = blockIdx.y * 8 + w;
    int r = lane >> 2, kq = (lane & 3) * 2;
    int row0 = mb * 16;
    uint8_t* dst = g_A8 + (((size_t)mb * 64 + kc) * 2048) + (size_t)lane * 64;
    int cnt0 = 0, cnt8 = 0;
#pragma unroll
    for (int kt = 0; kt < 8; kt++) {
        int k0 = kc * 128 + kt * 16 + kq;
        int2 p00 = *(const int2*)&adj[(size_t)(row0 + r) * N_NODES + k0];
        int2 p08 = *(const int2*)&adj[(size_t)(row0 + r) * N_NODES + k0 + 8];
        int2 p80 = *(const int2*)&adj[(size_t)(row0 + r + 8) * N_NODES + k0];
        int2 p88 = *(const int2*)&adj[(size_t)(row0 + r + 8) * N_NODES + k0 + 8];
        uint32_t b0 = (p00.x != 0), b1 = (p00.y != 0);
        uint32_t b2 = (p80.x != 0), b3 = (p80.y != 0);
        uint32_t b4 = (p08.x != 0), b5 = (p08.y != 0);
        uint32_t b6 = (p88.x != 0), b7 = (p88.y != 0);
        cnt0 += b0 + b1 + b4 + b5;
        cnt8 += b2 + b3 + b6 + b7;
        uint32_t w0 = b0 | (b1 << 8) | (b2 << 16) | (b3 << 24);
        uint32_t w1 = b4 | (b5 << 8) | (b6 << 16) | (b7 << 24);
        *(uint2*)(dst + kt * 8) = make_uint2(w0, w1);
    }
    cnt0 += __shfl_down_sync(0xffffffffu, cnt0, 2, 4);
    cnt0 += __shfl_down_sync(0xffffffffu, cnt0, 1, 4);
    cnt8 += __shfl_down_sync(0xffffffffu, cnt8, 2, 4);
    cnt8 += __shfl_down_sync(0xffffffffu, cnt8, 1, 4);
    if ((lane & 3) == 0) {
        atomicAdd(&g_deg[row0 + r], (float)cnt0);
        atomicAdd(&g_deg[row0 + r + 8], (float)cnt8);
    }
}

// ---------------- h -> hi/lo bf16 B image [j][64] ----------------
__global__ void k_h2bf() {
    int idx = blockIdx.x * 256 + threadIdx.x;
    int j = idx >> 5, e = idx & 31;
    float h = g_h[idx];
    __nv_bfloat16 hi = __float2bfloat16(h);
    __nv_bfloat16 lo = __float2bfloat16(h - __bfloat162float(hi));
    g_hT[j * 64 + e] = hi;
    g_hT[j * 64 + 32 + e] = lo;
}

// ---------------- nei partials = A @ [h_hi | h_lo] via mma.sync bf16 ----------------
// grid (64 mtiles, 2 khalves), 256 threads = 8 warps (4m x 2n).
#define NEI_SMEM (4 * 16384)
__global__ void __launch_bounds__(256, 1) k_neimma() {
    extern __shared__ uint8_t smem[];
    uint32_t sb = smem_u32(smem);
    int t = threadIdx.x, lane = t & 31, w = t >> 5;
    int mw = w & 3, nw = w >> 2;
    int mtile = blockIdx.x, khalf = blockIdx.y;

    const uint8_t* Abase = g_A8 +
        (((size_t)(mtile * 8 + mw * 2) * 64 + khalf * 32) * 2048) + (size_t)lane * 64;
    const uint8_t* Bglob = (const uint8_t*)g_hT + (size_t)khalf * 4096 * 128;

    // B stage loader: 16KB = 1024 x 16B, swizzle block = cg ^ (krow & 7)
#define LOADB(c, s)                                                              \
    {                                                                            \
        uint32_t dstb = sb + (s) * 16384;                                        \
        const uint8_t* srcb = Bglob + (size_t)(c) * 128 * 128;                   \
        _Pragma("unroll")                                                        \
        for (int i = 0; i < 4; i++) {                                            \
            int idx = t + i * 256;                                               \
            int kr = idx >> 3, cg = idx & 7;                                     \
            cp16(dstb + kr * 128 + (((uint32_t)(cg ^ (kr & 7))) << 4),           \
                 srcb + (size_t)kr * 128 + cg * 16);                             \
        }                                                                        \
        asm volatile("cp.async.commit_group;");                                  \
    }

    uint4 Acur[2][4], Anxt[2][4];
#pragma unroll
    for (int mt = 0; mt < 2; mt++) {
        const uint4* p = (const uint4*)(Abase + (size_t)mt * 131072);
#pragma unroll
        for (int i = 0; i < 4; i++) Acur[mt][i] = p[i];
    }
    LOADB(0, 0);
    LOADB(1, 1);
    LOADB(2, 2);

    float acc[2][4][4];
#pragma unroll
    for (int mt = 0; mt < 2; mt++)
#pragma unroll
        for (int n8 = 0; n8 < 4; n8++)
#pragma unroll
            for (int i = 0; i < 4; i++) acc[mt][n8][i] = 0.f;

    for (int c = 0; c < 32; c++) {
        if (c < 31) {
#pragma unroll
            for (int mt = 0; mt < 2; mt++) {
                const uint4* p =
                    (const uint4*)(Abase + (size_t)mt * 131072 + (size_t)(c + 1) * 2048);
#pragma unroll
                for (int i = 0; i < 4; i++) Anxt[mt][i] = p[i];
            }
        }
        asm volatile("cp.async.wait_group 2;");
        __syncthreads();
        uint32_t sbase = sb + (c & 3) * 16384;
        int krb = lane & 15;
#pragma unroll
        for (int kt = 0; kt < 8; kt++) {
            int krow = kt * 16 + krb;
            uint32_t rowaddr = sbase + krow * 128;
            uint32_t bfr[4][2];
#pragma unroll
            for (int n8 = 0; n8 < 4; n8++) {
                int n8abs = nw * 4 + n8;
                ldm_x2_trans(bfr[n8], rowaddr + (((uint32_t)(n8abs ^ (krow & 7))) << 4));
            }
#pragma unroll
            for (int mt = 0; mt < 2; mt++) {
                uint4 q = Acur[mt][kt >> 1];
                uint32_t w0 = (kt & 1) ? q.z : q.x;
                uint32_t w1 = (kt & 1) ? q.w : q.y;
                uint32_t a0 = prmt0(w0, 0x4140) * 0x3F80u;
                uint32_t a1 = prmt0(w0, 0x4342) * 0x3F80u;
                uint32_t a2 = prmt0(w1, 0x4140) * 0x3F80u;
                uint32_t a3 = prmt0(w1, 0x4342) * 0x3F80u;
#pragma unroll
                for (int n8 = 0; n8 < 4; n8++)
                    mma_bf16(acc[mt][n8], a0, a1, a2, a3, bfr[n8][0], bfr[n8][1]);
            }
        }
        __syncthreads();
        if (c + 3 < 32) LOADB(c + 3, (c + 3) & 3);
        if (c < 31) {
#pragma unroll
            for (int mt = 0; mt < 2; mt++)
#pragma unroll
                for (int i = 0; i < 4; i++) Acur[mt][i] = Anxt[mt][i];
        }
    }

    // epilogue: write partials [khalf*2+nw][node][col]
    float* base = g_neip[khalf * 2 + nw];
    int r = lane >> 2, c0 = (lane & 3) * 2;
#pragma unroll
    for (int mt = 0; mt < 2; mt++) {
        int node0 = mtile * 128 + mw * 32 + mt * 16 + r;
#pragma unroll
        for (int n8 = 0; n8 < 4; n8++) {
            int col = n8 * 8 + c0;
            *(float2*)&base[(size_t)node0 * 32 + col] =
                make_float2(acc[mt][n8][0], acc[mt][n8][1]);
            *(float2*)&base[(size_t)(node0 + 8) * 32 + col] =
                make_float2(acc[mt][n8][2], acc[mt][n8][3]);
        }
    }
#undef LOADB
}

// ---------------- msg = [h | nei_mean] @ msg_W^T + b (zero if no neighbors) -------
#define MSG_SMEM_FLOATS (64 * 68 + 64 * 260)
__global__ void __launch_bounds__(256) k_msg(const float* __restrict__ Wd,
                                             const float* __restrict__ bd) {
    extern __shared__ float sm[];
    float* x_s = sm;             // [64][68]
    float* W_s = sm + 64 * 68;   // [k=64][o pitch 260]
    int row0 = blockIdx.x * 64;
    int t = threadIdx.x;
    for (int idx = t; idx < 64 * EMBED; idx += 256) {
        int r = idx >> 5, e = idx & 31;
        int node = row0 + r;
        float invd = 1.0f / fmaxf(g_deg[node], 1.0f);
        int o = node * 32 + e;
        x_s[r * 68 + e] = g_h[node * EMBED + e];
        x_s[r * 68 + 32 + e] =
            (g_neip[0][o] + g_neip[1][o] + g_neip[2][o] + g_neip[3][o]) * invd;
    }
    for (int idx = t; idx < HIDDEN * 64; idx += 256) {
        int o = idx >> 6, k = idx & 63;
        W_s[k * 260 + o] = Wd[idx];
    }
    __syncthreads();
    int rb = (t >> 5) * 8;
    int obA = (t & 31) * 4;
    int obB = 128 + obA;
    float acc[8][8];
#pragma unroll
    for (int i = 0; i < 8; i++)
#pragma unroll
        for (int j = 0; j < 8; j++) acc[i][j] = 0.f;
    for (int k = 0; k < 64; k++) {
        float4 wA = *(const float4*)&W_s[k * 260 + obA];
        float4 wB = *(const float4*)&W_s[k * 260 + obB];
#pragma unroll
        for (int i = 0; i < 8; i++) {
            float x = x_s[(rb + i) * 68 + k];
            acc[i][0] = fmaf(x, wA.x, acc[i][0]);
            acc[i][1] = fmaf(x, wA.y, acc[i][1]);
            acc[i][2] = fmaf(x, wA.z, acc[i][2]);
            acc[i][3] = fmaf(x, wA.w, acc[i][3]);
            acc[i][4] = fmaf(x, wB.x, acc[i][4]);
            acc[i][5] = fmaf(x, wB.y, acc[i][5]);
            acc[i][6] = fmaf(x, wB.z, acc[i][6]);
            acc[i][7] = fmaf(x, wB.w, acc[i][7]);
        }
    }
    float4 bA = *(const float4*)&bd[obA];
    float4 bB = *(const float4*)&bd[obB];
#pragma unroll
    for (int i = 0; i < 8; i++) {
        int node = row0 + rb + i;
        float hn = g_deg[node] > 0.f ? 1.f : 0.f;
        float4 oA, oB;
        oA.x = (acc[i][0] + bA.x) * hn; oA.y = (acc[i][1] + bA.y) * hn;
        oA.z = (acc[i][2] + bA.z) * hn; oA.w = (acc[i][3] + bA.w) * hn;
        oB.x = (acc[i][4] + bB.x) * hn; oB.y = (acc[i][5] + bB.y) * hn;
        oB.z = (acc[i][6] + bB.z) * hn; oB.w = (acc[i][7] + bB.w) * hn;
        *(float4*)&g_msg[(size_t)node * HIDDEN + obA] = oA;
        *(float4*)&g_msg[(size_t)node * HIDDEN + obB] = oB;
    }
}

// ---------------- GRU step, gates in registers ----------------
#define GRU_SMEM_FLOATS (64 * 256 + 64 * 33 + 256 * 100 + 32 * 100)
__global__ void __launch_bounds__(256) k_gru(const float* __restrict__ Wih,
                                             const float* __restrict__ Whh,
                                             const float* __restrict__ bih,
                                             const float* __restrict__ bhh) {
    extern __shared__ float sm[];
    float* msg_s = sm;                     // [64][256]
    float* h_s   = msg_s + 64 * 256;       // [64][33]
    float* Wih_s = h_s + 64 * 33;          // [k=256][g pitch 100]
    float* Whh_s = Wih_s + 256 * 100;      // [k=32][g pitch 100]
    int row0 = blockIdx.x * 64;
    int t = threadIdx.x;
    for (int idx = t; idx < 64 * HIDDEN; idx += 256) {
        int r = idx >> 8;
        msg_s[idx] = g_msg[(size_t)(row0 + r) * HIDDEN + (idx & 255)];
    }
    for (int idx = t; idx < 64 * EMBED; idx += 256) {
        int r = idx >> 5, c = idx & 31;
        h_s[r * 33 + c] = g_h[(size_t)(row0 + r) * EMBED + c];
    }
    for (int idx = t; idx < 96 * HIDDEN; idx += 256) {
        int g = idx >> 8, k = idx & 255;
        Wih_s[k * 100 + g] = Wih[idx];
    }
    for (int idx = t; idx < 96 * EMBED; idx += 256) {
        int g = idx >> 5, k = idx & 31;
        Whh_s[k * 100 + g] = Whh[idx];
    }
    __syncthreads();
    int e = t & 31;
    int rb = (t >> 5) * 8;
    float gi[8][3], gh[8][3];
#pragma unroll
    for (int i = 0; i < 8; i++) {
        gi[i][0] = gi[i][1] = gi[i][2] = 0.f;
        gh[i][0] = gh[i][1] = gh[i][2] = 0.f;
    }
    for (int k = 0; k < HIDDEN; k++) {
        float w0 = Wih_s[k * 100 + e];
        float w1 = Wih_s[k * 100 + 32 + e];
        float w2 = Wih_s[k * 100 + 64 + e];
#pragma unroll
        for (int i = 0; i < 8; i++) {
            float m = msg_s[(rb + i) * 256 + k];
            gi[i][0] = fmaf(m, w0, gi[i][0]);
            gi[i][1] = fmaf(m, w1, gi[i][1]);
            gi[i][2] = fmaf(m, w2, gi[i][2]);
        }
    }
    for (int k = 0; k < EMBED; k++) {
        float w0 = Whh_s[k * 100 + e];
        float w1 = Whh_s[k * 100 + 32 + e];
        float w2 = Whh_s[k * 100 + 64 + e];
#pragma unroll
        for (int i = 0; i < 8; i++) {
            float hv = h_s[(rb + i) * 33 + k];
            gh[i][0] = fmaf(hv, w0, gh[i][0]);
            gh[i][1] = fmaf(hv, w1, gh[i][1]);
            gh[i][2] = fmaf(hv, w2, gh[i][2]);
        }
    }
    float bi0 = bih[e], bi1 = bih[32 + e], bi2 = bih[64 + e];
    float bh0 = bhh[e], bh1 = bhh[32 + e], bh2 = bhh[64 + e];
#pragma unroll
    for (int i = 0; i < 8; i++) {
        float rg = 1.f / (1.f + expf(-((gi[i][0] + bi0) + (gh[i][0] + bh0))));
        float z  = 1.f / (1.f + expf(-((gi[i][1] + bi1) + (gh[i][1] + bh1))));
        float n  = tanhf((gi[i][2] + bi2) + rg * (gh[i][2] + bh2));
        float hp = h_s[(rb + i) * 33 + e];
        g_h[(size_t)(row0 + rb + i) * EMBED + e] = (1.f - z) * n + z * hp;
    }
}

// ---------------- pooling ----------------
__global__ void k_pool(const int* __restrict__ bidx, float* __restrict__ out) {
    int idx = blockIdx.x * 256 + threadIdx.x;
    if (idx < N_NODES * EMBED) {
        int n = idx >> 5, e = idx & 31;
        float v = g_h[idx];
        out[idx] = v;
        int b = bidx[n];
        atomicAdd(&g_pool_sum[b * EMBED + e], v);
        if (e == 0) atomicAdd(&g_pool_cnt[b], 1.0f);
    }
}

__global__ void __launch_bounds__(256) k_graph(const float* __restrict__ pW,
                                               const float* __restrict__ pb,
                                               float* __restrict__ out) {
    __shared__ float mean[EMBED];
    __shared__ float Ws[EMBED * HIDDEN];
    int b = blockIdx.x;
    int t = threadIdx.x;
    for (int idx = t; idx < HIDDEN * EMBED; idx += 256) {
        int o = idx >> 5, e = idx & 31;
        Ws[e * HIDDEN + o] = pW[idx];
    }
    if (t < EMBED) {
        float cnt = g_pool_cnt[b];
        mean[t] = cnt > 0.f ? g_pool_sum[b * EMBED + t] / cnt : 0.f;
    }
    __syncthreads();
    float acc = pb[t];
#pragma unroll
    for (int e = 0; e < EMBED; e++) acc = fmaf(mean[e], Ws[e * HIDDEN + t], acc);
    out[(size_t)(N_NODES * EMBED + N_BONDS * EMBED) + b * HIDDEN + t] = acc;
}

// ---------------- launch ----------------
extern "C" void kernel_launch(void* const* d_in, const int* in_sizes, int n_in,
                              void* d_out, int out_size) {
    const int* af    = (const int*)d_in[0];
    const int* bf    = (const int*)d_in[1];
    const int* adj   = (const int*)d_in[2];
    const int* bidx  = (const int*)d_in[3];
    const float* atab = (const float*)d_in[4];
    const float* btab = (const float*)d_in[5];
    const float* msgW = (const float*)d_in[6];
    const float* msgb = (const float*)d_in[7];
    const float* Wih  = (const float*)d_in[8];
    const float* Whh  = (const float*)d_in[9];
    const float* bih  = (const float*)d_in[10];
    const float* bhh  = (const float*)d_in[11];
    const float* pW   = (const float*)d_in[12];
    const float* pb   = (const float*)d_in[13];
    float* out = (float*)d_out;

    cudaFuncSetAttribute(k_neimma, cudaFuncAttributeMaxDynamicSharedMemorySize, NEI_SMEM);
    cudaFuncSetAttribute(k_msg, cudaFuncAttributeMaxDynamicSharedMemorySize,
                         MSG_SMEM_FLOATS * 4);
    cudaFuncSetAttribute(k_gru, cudaFuncAttributeMaxDynamicSharedMemorySize,
                         GRU_SMEM_FLOATS * 4);

    k_init<<<(N_BONDS * EMBED + 255) / 256, 256>>>(af, bf, atab, btab, out);
    k_convA<<<dim3(512, 8), 256>>>(adj);
    for (int d = 0; d < DEPTH; ++d) {
        k_h2bf<<<(N_NODES * EMBED) / 256, 256>>>();
        k_neimma<<<dim3(64, 2), 256, NEI_SMEM>>>();
        k_msg<<<N_NODES / 64, 256, MSG_SMEM_FLOATS * 4>>>(msgW + d * HIDDEN * 64,
                                                          msgb + d * HIDDEN);
        k_gru<<<N_NODES / 64, 256, GRU_SMEM_FLOATS * 4>>>(
            Wih + d * 96 * HIDDEN, Whh + d * 96 * EMBED, bih + d * 96, bhh + d * 96);
    }
    k_pool<<<(N_NODES * EMBED + 255) / 256, 256>>>(bidx, out);
    k_graph<<<NUM_GRAPHS, HIDDEN>>>(pW, pb, out);
}

// round 4
// speedup vs baseline: 4.4032x; 1.1521x over previous
#include <cuda_runtime.h>
#include <cuda_bf16.h>
#include <math.h>
#include <stdint.h>

#define N_NODES 8192
#define N_BONDS 16384
#define EMBED 32
#define HIDDEN 256
#define DEPTH 10
#define NUM_GRAPHS 256

// ---------------- static device scratch ----------------
// A image: fragment-ordered int8 {0,1}. Block (mb 0..511, kc 0..63) = 2048B:
//   [lane 32][kt 8][8 bytes] in m16n8k16 a-frag order.
__device__ __align__(16) uint8_t g_A8[(size_t)512 * 64 * 2048];  // 64MB
__device__ __align__(16) __nv_bfloat16 g_hT[N_NODES * 64];       // [j][hi32|lo32]
__device__ __align__(16) float g_h[N_NODES * EMBED];
__device__ __align__(16) float g_neip[8][N_NODES * EMBED];       // [kq*2+nw]
__device__ float g_deg[N_NODES];
__device__ float g_pool_sum[NUM_GRAPHS * EMBED];
__device__ float g_pool_cnt[NUM_GRAPHS];

// ---------------- PTX helpers ----------------
__device__ __forceinline__ uint32_t smem_u32(const void* p) {
    uint32_t a;
    asm("{ .reg .u64 t; cvta.to.shared.u64 t, %1; cvt.u32.u64 %0, t; }" : "=r"(a) : "l"(p));
    return a;
}
__device__ __forceinline__ uint32_t prmt0(uint32_t a, uint32_t sel) {
    uint32_t d;
    asm("prmt.b32 %0, %1, 0, %2;" : "=r"(d) : "r"(a), "r"(sel));
    return d;
}
__device__ __forceinline__ void cp16(uint32_t dst, const void* src) {
    asm volatile("cp.async.cg.shared.global [%0], [%1], 16;" :: "r"(dst), "l"(src));
}
__device__ __forceinline__ void ldm_x4_trans(uint32_t* r, uint32_t addr) {
    asm volatile("ldmatrix.sync.aligned.m8n8.x4.trans.shared.b16 {%0,%1,%2,%3}, [%4];"
                 : "=r"(r[0]), "=r"(r[1]), "=r"(r[2]), "=r"(r[3]) : "r"(addr));
}
__device__ __forceinline__ void mma_bf16(float* c, uint32_t a0, uint32_t a1,
                                         uint32_t a2, uint32_t a3,
                                         uint32_t b0, uint32_t b1) {
    asm volatile(
        "mma.sync.aligned.m16n8k16.row.col.f32.bf16.bf16.f32 "
        "{%0,%1,%2,%3}, {%4,%5,%6,%7}, {%8,%9}, {%0,%1,%2,%3};"
        : "+f"(c[0]), "+f"(c[1]), "+f"(c[2]), "+f"(c[3])
        : "r"(a0), "r"(a1), "r"(a2), "r"(a3), "r"(b0), "r"(b1));
}

// ---------------- init ----------------
__global__ void k_init(const int* __restrict__ af, const int* __restrict__ bf,
                       const float* __restrict__ atab, const float* __restrict__ btab,
                       float* __restrict__ out) {
    int idx = blockIdx.x * 256 + threadIdx.x;
    if (idx < N_BONDS * EMBED)
        out[N_NODES * EMBED + idx] = btab[bf[idx >> 5] * EMBED + (idx & 31)];
    if (idx < N_NODES * EMBED)
        g_h[idx] = atab[af[idx >> 5] * EMBED + (idx & 31)];
    if (idx < N_NODES) g_deg[idx] = 0.f;
    if (idx < NUM_GRAPHS * EMBED) g_pool_sum[idx] = 0.f;
    if (idx < NUM_GRAPHS) g_pool_cnt[idx] = 0.f;
}

// ---------------- adjacency -> fragment-ordered int8 image + degree ----------------
__global__ void __launch_bounds__(256) k_convA(const int* __restrict__ adj) {
    int t = threadIdx.x, lane = t & 31, w = t >> 5;
    int mb = blockIdx.x;
    int kc = blockIdx.y * 8 + w;
    int r = lane >> 2, kq = (lane & 3) * 2;
    int row0 = mb * 16;
    uint8_t* dst = g_A8 + (((size_t)mb * 64 + kc) * 2048) + (size_t)lane * 64;
    int cnt0 = 0, cnt8 = 0;
#pragma unroll
    for (int kt = 0; kt < 8; kt++) {
        int k0 = kc * 128 + kt * 16 + kq;
        int2 p00 = *(const int2*)&adj[(size_t)(row0 + r) * N_NODES + k0];
        int2 p08 = *(const int2*)&adj[(size_t)(row0 + r) * N_NODES + k0 + 8];
        int2 p80 = *(const int2*)&adj[(size_t)(row0 + r + 8) * N_NODES + k0];
        int2 p88 = *(const int2*)&adj[(size_t)(row0 + r + 8) * N_NODES + k0 + 8];
        uint32_t b0 = (p00.x != 0), b1 = (p00.y != 0);
        uint32_t b2 = (p80.x != 0), b3 = (p80.y != 0);
        uint32_t b4 = (p08.x != 0), b5 = (p08.y != 0);
        uint32_t b6 = (p88.x != 0), b7 = (p88.y != 0);
        cnt0 += b0 + b1 + b4 + b5;
        cnt8 += b2 + b3 + b6 + b7;
        uint32_t w0 = b0 | (b1 << 8) | (b2 << 16) | (b3 << 24);
        uint32_t w1 = b4 | (b5 << 8) | (b6 << 16) | (b7 << 24);
        *(uint2*)(dst + kt * 8) = make_uint2(w0, w1);
    }
    cnt0 += __shfl_down_sync(0xffffffffu, cnt0, 2, 4);
    cnt0 += __shfl_down_sync(0xffffffffu, cnt0, 1, 4);
    cnt8 += __shfl_down_sync(0xffffffffu, cnt8, 2, 4);
    cnt8 += __shfl_down_sync(0xffffffffu, cnt8, 1, 4);
    if ((lane & 3) == 0) {
        atomicAdd(&g_deg[row0 + r], (float)cnt0);
        atomicAdd(&g_deg[row0 + r + 8], (float)cnt8);
    }
}

// ---------------- h -> hi/lo bf16 B image (once; loop updates come from k_msgru) ----
__global__ void k_h2bf() {
    int idx = blockIdx.x * 256 + threadIdx.x;
    int j = idx >> 5, e = idx & 31;
    float h = g_h[idx];
    __nv_bfloat16 hi = __float2bfloat16(h);
    __nv_bfloat16 lo = __float2bfloat16(h - __bfloat162float(hi));
    g_hT[j * 64 + e] = hi;
    g_hT[j * 64 + 32 + e] = lo;
}

// ---------------- nei partials = A @ [h_hi | h_lo] via mma.sync bf16 ----------------
// grid (64 mtiles, 4 kquarters), 256 threads = 8 warps (4m x 2n), 2 CTAs/SM.
#define NEI_SMEM (4 * 16384)
#define NEI_CHUNKS 16
__global__ void __launch_bounds__(256, 2) k_neimma() {
    extern __shared__ uint8_t smem[];
    uint32_t sb = smem_u32(smem);
    int t = threadIdx.x, lane = t & 31, w = t >> 5;
    int mw = w & 3, nw = w >> 2;
    int mtile = blockIdx.x, kq = blockIdx.y;

    const uint8_t* Abase = g_A8 +
        (((size_t)(mtile * 8 + mw * 2) * 64 + kq * 16) * 2048) + (size_t)lane * 64;
    const uint8_t* Bglob = (const uint8_t*)g_hT + (size_t)kq * 1024 * 128;

#define LOADB(c, s)                                                              \
    {                                                                            \
        uint32_t dstb = sb + (s) * 16384;                                        \
        const uint8_t* srcb = Bglob + (size_t)(c) * 128 * 128;                   \
        _Pragma("unroll")                                                        \
        for (int i = 0; i < 4; i++) {                                            \
            int idx = t + i * 256;                                               \
            int kr = idx >> 3, cg = idx & 7;                                     \
            cp16(dstb + kr * 128 + (((uint32_t)(cg ^ (kr & 7))) << 4),           \
                 srcb + (size_t)kr * 128 + cg * 16);                             \
        }                                                                        \
        asm volatile("cp.async.commit_group;");                                  \
    }

    LOADB(0, 0);
    LOADB(1, 1);
    LOADB(2, 2);

    float acc[2][4][4];
#pragma unroll
    for (int mt = 0; mt < 2; mt++)
#pragma unroll
        for (int n8 = 0; n8 < 4; n8++)
#pragma unroll
            for (int i = 0; i < 4; i++) acc[mt][n8][i] = 0.f;

    int krb = lane & 15;
    int chi = lane >> 4;

    for (int c = 0; c < NEI_CHUNKS; c++) {
        // issue A loads for this chunk; latency covered by cp.async wait below
        uint4 Acur[2][4];
#pragma unroll
        for (int mt = 0; mt < 2; mt++) {
            const uint4* p = (const uint4*)(Abase + (size_t)mt * 131072 + (size_t)c * 2048);
#pragma unroll
            for (int i = 0; i < 4; i++) Acur[mt][i] = p[i];
        }
        asm volatile("cp.async.wait_group 2;");
        __syncthreads();
        uint32_t sbase = sb + (c & 3) * 16384;
#pragma unroll
        for (int kt = 0; kt < 8; kt++) {
            int krow = kt * 16 + krb;
            uint32_t rowaddr = sbase + krow * 128;
            uint32_t bfr[2][4];
#pragma unroll
            for (int p = 0; p < 2; p++) {
                int cblk = nw * 4 + p * 2 + chi;
                ldm_x4_trans(bfr[p], rowaddr + (((uint32_t)(cblk ^ (krow & 7))) << 4));
            }
#pragma unroll
            for (int mt = 0; mt < 2; mt++) {
                uint4 q = Acur[mt][kt >> 1];
                uint32_t w0 = (kt & 1) ? q.z : q.x;
                uint32_t w1 = (kt & 1) ? q.w : q.y;
                uint32_t a0 = prmt0(w0, 0x4140) * 0x3F80u;
                uint32_t a1 = prmt0(w0, 0x4342) * 0x3F80u;
                uint32_t a2 = prmt0(w1, 0x4140) * 0x3F80u;
                uint32_t a3 = prmt0(w1, 0x4342) * 0x3F80u;
                mma_bf16(acc[mt][0], a0, a1, a2, a3, bfr[0][0], bfr[0][1]);
                mma_bf16(acc[mt][1], a0, a1, a2, a3, bfr[0][2], bfr[0][3]);
                mma_bf16(acc[mt][2], a0, a1, a2, a3, bfr[1][0], bfr[1][1]);
                mma_bf16(acc[mt][3], a0, a1, a2, a3, bfr[1][2], bfr[1][3]);
            }
        }
        __syncthreads();
        if (c + 3 < NEI_CHUNKS) LOADB(c + 3, (c + 3) & 3);
    }

    float* base = g_neip[kq * 2 + nw];
    int r = lane >> 2, c0 = (lane & 3) * 2;
#pragma unroll
    for (int mt = 0; mt < 2; mt++) {
        int node0 = mtile * 128 + mw * 32 + mt * 16 + r;
#pragma unroll
        for (int n8 = 0; n8 < 4; n8++) {
            int col = n8 * 8 + c0;
            *(float2*)&base[(size_t)node0 * 32 + col] =
                make_float2(acc[mt][n8][0], acc[mt][n8][1]);
            *(float2*)&base[(size_t)(node0 + 8) * 32 + col] =
                make_float2(acc[mt][n8][2], acc[mt][n8][3]);
        }
    }
#undef LOADB
}

// ---------------- fused msg + GRU + hi/lo repack ----------------
// 64 nodes/block, 128 blocks, 256 threads. SMEM phases:
//   x_s [64][68] (h || nei_mean), msg_s [64][256],
//   wbuf: phase1 msgW [k=64][260], phase2 Wih [k=256][102], whh [k=32][102]
#define WBUF_FLOATS 26112
#define MSGRU_SMEM_FLOATS (64 * 68 + 64 * 256 + WBUF_FLOATS + 32 * 102)
__global__ void __launch_bounds__(256) k_msgru(const float* __restrict__ Wd,
                                               const float* __restrict__ bd,
                                               const float* __restrict__ Wih,
                                               const float* __restrict__ Whh,
                                               const float* __restrict__ bih,
                                               const float* __restrict__ bhh) {
    extern __shared__ float sm[];
    float* x_s = sm;                       // [64][68]
    float* msg_s = x_s + 64 * 68;          // [64][256]
    float* wbuf = msg_s + 64 * 256;        // phase-shared weight buffer
    float* whh_s = wbuf + WBUF_FLOATS;     // [32][102]
    int row0 = blockIdx.x * 64;
    int t = threadIdx.x;

    // stage x = [h | nei_mean]
    for (int idx = t; idx < 64 * EMBED; idx += 256) {
        int r = idx >> 5, e = idx & 31;
        int node = row0 + r;
        float invd = 1.0f / fmaxf(g_deg[node], 1.0f);
        int o = node * 32 + e;
        float s = g_neip[0][o] + g_neip[1][o] + g_neip[2][o] + g_neip[3][o] +
                  g_neip[4][o] + g_neip[5][o] + g_neip[6][o] + g_neip[7][o];
        x_s[r * 68 + e] = g_h[node * EMBED + e];
        x_s[r * 68 + 32 + e] = s * invd;
    }
    // stage msg weights transposed
    for (int idx = t; idx < HIDDEN * 64; idx += 256) {
        int o = idx >> 6, k = idx & 63;
        wbuf[k * 260 + o] = Wd[idx];
    }
    __syncthreads();

    // phase 1: msg -> msg_s
    {
        int rb = (t >> 5) * 8;
        int obA = (t & 31) * 4;
        int obB = 128 + obA;
        float acc[8][8];
#pragma unroll
        for (int i = 0; i < 8; i++)
#pragma unroll
            for (int j = 0; j < 8; j++) acc[i][j] = 0.f;
        for (int k = 0; k < 64; k++) {
            float4 wA = *(const float4*)&wbuf[k * 260 + obA];
            float4 wB = *(const float4*)&wbuf[k * 260 + obB];
#pragma unroll
            for (int i = 0; i < 8; i++) {
                float x = x_s[(rb + i) * 68 + k];
                acc[i][0] = fmaf(x, wA.x, acc[i][0]);
                acc[i][1] = fmaf(x, wA.y, acc[i][1]);
                acc[i][2] = fmaf(x, wA.z, acc[i][2]);
                acc[i][3] = fmaf(x, wA.w, acc[i][3]);
                acc[i][4] = fmaf(x, wB.x, acc[i][4]);
                acc[i][5] = fmaf(x, wB.y, acc[i][5]);
                acc[i][6] = fmaf(x, wB.z, acc[i][6]);
                acc[i][7] = fmaf(x, wB.w, acc[i][7]);
            }
        }
        float4 bA = *(const float4*)&bd[obA];
        float4 bB = *(const float4*)&bd[obB];
#pragma unroll
        for (int i = 0; i < 8; i++) {
            int node = row0 + rb + i;
            float hn = g_deg[node] > 0.f ? 1.f : 0.f;
            float4 oA, oB;
            oA.x = (acc[i][0] + bA.x) * hn; oA.y = (acc[i][1] + bA.y) * hn;
            oA.z = (acc[i][2] + bA.z) * hn; oA.w = (acc[i][3] + bA.w) * hn;
            oB.x = (acc[i][4] + bB.x) * hn; oB.y = (acc[i][5] + bB.y) * hn;
            oB.z = (acc[i][6] + bB.z) * hn; oB.w = (acc[i][7] + bB.w) * hn;
            *(float4*)&msg_s[(rb + i) * 256 + obA] = oA;
            *(float4*)&msg_s[(rb + i) * 256 + obB] = oB;
        }
    }
    __syncthreads();

    // stage GRU weights (overwrite wbuf)
    for (int idx = t; idx < 96 * HIDDEN; idx += 256) {
        int g = idx >> 8, k = idx & 255;
        wbuf[k * 102 + g] = Wih[idx];
    }
    for (int idx = t; idx < 96 * EMBED; idx += 256) {
        int g = idx >> 5, k = idx & 31;
        whh_s[k * 102 + g] = Whh[idx];
    }
    __syncthreads();

    // phase 2: GRU gates in registers
    {
        int e = t & 31;
        int rb = (t >> 5) * 8;
        float gi[8][3], gh[8][3];
#pragma unroll
        for (int i = 0; i < 8; i++) {
            gi[i][0] = gi[i][1] = gi[i][2] = 0.f;
            gh[i][0] = gh[i][1] = gh[i][2] = 0.f;
        }
        for (int k = 0; k < HIDDEN; k++) {
            float w0 = wbuf[k * 102 + e];
            float w1 = wbuf[k * 102 + 32 + e];
            float w2 = wbuf[k * 102 + 64 + e];
#pragma unroll
            for (int i = 0; i < 8; i++) {
                float m = msg_s[(rb + i) * 256 + k];
                gi[i][0] = fmaf(m, w0, gi[i][0]);
                gi[i][1] = fmaf(m, w1, gi[i][1]);
                gi[i][2] = fmaf(m, w2, gi[i][2]);
            }
        }
        for (int k = 0; k < EMBED; k++) {
            float w0 = whh_s[k * 102 + e];
            float w1 = whh_s[k * 102 + 32 + e];
            float w2 = whh_s[k * 102 + 64 + e];
#pragma unroll
            for (int i = 0; i < 8; i++) {
                float hv = x_s[(rb + i) * 68 + k];
                gh[i][0] = fmaf(hv, w0, gh[i][0]);
                gh[i][1] = fmaf(hv, w1, gh[i][1]);
                gh[i][2] = fmaf(hv, w2, gh[i][2]);
            }
        }
        float bi0 = bih[e], bi1 = bih[32 + e], bi2 = bih[64 + e];
        float bh0 = bhh[e], bh1 = bhh[32 + e], bh2 = bhh[64 + e];
#pragma unroll
        for (int i = 0; i < 8; i++) {
            float rg = 1.f / (1.f + expf(-((gi[i][0] + bi0) + (gh[i][0] + bh0))));
            float z  = 1.f / (1.f + expf(-((gi[i][1] + bi1) + (gh[i][1] + bh1))));
            float n  = tanhf((gi[i][2] + bi2) + rg * (gh[i][2] + bh2));
            float hp = x_s[(rb + i) * 68 + e];
            float hnew = (1.f - z) * n + z * hp;
            int node = row0 + rb + i;
            g_h[(size_t)node * EMBED + e] = hnew;
            __nv_bfloat16 hi = __float2bfloat16(hnew);
            __nv_bfloat16 lo = __float2bfloat16(hnew - __bfloat162float(hi));
            g_hT[node * 64 + e] = hi;
            g_hT[node * 64 + 32 + e] = lo;
        }
    }
}

// ---------------- pooling ----------------
__global__ void k_pool(const int* __restrict__ bidx, float* __restrict__ out) {
    int idx = blockIdx.x * 256 + threadIdx.x;
    if (idx < N_NODES * EMBED) {
        int n = idx >> 5, e = idx & 31;
        float v = g_h[idx];
        out[idx] = v;
        int b = bidx[n];
        atomicAdd(&g_pool_sum[b * EMBED + e], v);
        if (e == 0) atomicAdd(&g_pool_cnt[b], 1.0f);
    }
}

__global__ void __launch_bounds__(256) k_graph(const float* __restrict__ pW,
                                               const float* __restrict__ pb,
                                               float* __restrict__ out) {
    __shared__ float mean[EMBED];
    __shared__ float Ws[EMBED * HIDDEN];
    int b = blockIdx.x;
    int t = threadIdx.x;
    for (int idx = t; idx < HIDDEN * EMBED; idx += 256) {
        int o = idx >> 5, e = idx & 31;
        Ws[e * HIDDEN + o] = pW[idx];
    }
    if (t < EMBED) {
        float cnt = g_pool_cnt[b];
        mean[t] = cnt > 0.f ? g_pool_sum[b * EMBED + t] / cnt : 0.f;
    }
    __syncthreads();
    float acc = pb[t];
#pragma unroll
    for (int e = 0; e < EMBED; e++) acc = fmaf(mean[e], Ws[e * HIDDEN + t], acc);
    out[(size_t)(N_NODES * EMBED + N_BONDS * EMBED) + b * HIDDEN + t] = acc;
}

// ---------------- launch ----------------
extern "C" void kernel_launch(void* const* d_in, const int* in_sizes, int n_in,
                              void* d_out, int out_size) {
    const int* af    = (const int*)d_in[0];
    const int* bf    = (const int*)d_in[1];
    const int* adj   = (const int*)d_in[2];
    const int* bidx  = (const int*)d_in[3];
    const float* atab = (const float*)d_in[4];
    const float* btab = (const float*)d_in[5];
    const float* msgW = (const float*)d_in[6];
    const float* msgb = (const float*)d_in[7];
    const float* Wih  = (const float*)d_in[8];
    const float* Whh  = (const float*)d_in[9];
    const float* bih  = (const float*)d_in[10];
    const float* bhh  = (const float*)d_in[11];
    const float* pW   = (const float*)d_in[12];
    const float* pb   = (const float*)d_in[13];
    float* out = (float*)d_out;

    cudaFuncSetAttribute(k_neimma, cudaFuncAttributeMaxDynamicSharedMemorySize, NEI_SMEM);
    cudaFuncSetAttribute(k_msgru, cudaFuncAttributeMaxDynamicSharedMemorySize,
                         MSGRU_SMEM_FLOATS * 4);

    k_init<<<(N_BONDS * EMBED + 255) / 256, 256>>>(af, bf, atab, btab, out);
    k_convA<<<dim3(512, 8), 256>>>(adj);
    k_h2bf<<<(N_NODES * EMBED) / 256, 256>>>();
    for (int d = 0; d < DEPTH; ++d) {
        k_neimma<<<dim3(64, 4), 256, NEI_SMEM>>>();
        k_msgru<<<N_NODES / 64, 256, MSGRU_SMEM_FLOATS * 4>>>(
            msgW + d * HIDDEN * 64, msgb + d * HIDDEN,
            Wih + d * 96 * HIDDEN, Whh + d * 96 * EMBED, bih + d * 96, bhh + d * 96);
    }
    k_pool<<<(N_NODES * EMBED + 255) / 256, 256>>>(bidx, out);
    k_graph<<<NUM_GRAPHS, HIDDEN>>>(pW, pb, out);
}